// round 11
// baseline (speedup 1.0000x reference)
#include <cuda_runtime.h>
#include <cstdint>

#define NCTA  128
#define NTHR  256
#define T_STEPS 512
#define BATCH 128
#define APAD  68      // A row stride: 68 % 32 == 4 -> 8 b-lanes hit distinct bank quads
#define WPAD  4       // W row pad: stride C*(K+4) floats -> distinct bank quads for 4 j-lanes

// ---- global scratch (static: no allocation allowed) ----
__device__ float g_xT[T_STEPS * BATCH * 512];     // [t][b][k] time-major input
__device__ float g_spk0[2][BATCH * 1024];         // parity-double-buffered spike planes
__device__ float g_spk1[2][BATCH * 1024];
__device__ int          g_count;
__device__ volatile int g_gen;

struct __align__(16) Smem {
    float w0[8 * (512 + WPAD)];   // [jl][k]  this CTA's 8 cols of W0 (padded rows)
    float w1[8 * (1024 + WPAD)];  // [jl][k]  8 cols of W1
    float w2[4 * (1024 + WPAD)];  // [jl][k]  4 cols of W2
    float a[2][BATCH * APAD];     // double-buffered A chunks [b][64k]
    float mem0[BATCH * 8], spk0[BATCH * 8];
    float mem1[BATCH * 8], spk1[BATCH * 8];
    float mem2[BATCH * 4], spk2[BATCH * 4];
};

// ---- packed dual-fp32 FMA (SASS FFMA2): 2 exact IEEE fp32 FMAs per instr ----
__device__ __forceinline__ void fma2(unsigned long long& d,
                                     unsigned long long a, unsigned long long b) {
    asm("fma.rn.f32x2 %0, %1, %2, %0;" : "+l"(d) : "l"(a), "l"(b));
}

// ---- cp.async helpers ----
__device__ __forceinline__ void cp_async16(void* sdst, const void* gsrc) {
    uint32_t s = (uint32_t)__cvta_generic_to_shared(sdst);
    asm volatile("cp.async.cg.shared.global [%0], [%1], 16;" :: "r"(s), "l"(gsrc) : "memory");
}
__device__ __forceinline__ void cp_commit() {
    asm volatile("cp.async.commit_group;" ::: "memory");
}
__device__ __forceinline__ void cp_wait1() {
    asm volatile("cp.async.wait_group 1;" ::: "memory");
}

// Stage one 64k x 128row A chunk (32 KB) into smem. 8 x 16B per thread.
__device__ __forceinline__ void stage_chunk(float* dst, const float* src, int stride) {
    const int tid = threadIdx.x;
#pragma unroll
    for (int i = 0; i < 8; ++i) {
        int flat = tid + i * NTHR;           // 0..2047 float4 slots
        int br = flat >> 4, k4 = flat & 15;
        cp_async16(dst + br * APAD + k4 * 4, src + (size_t)br * stride + k4 * 4);
    }
}

// ---- grid barrier: 128 CTAs, 1/SM, co-resident by construction ----
__device__ __forceinline__ void grid_sync()
{
    __threadfence();
    __syncthreads();
    if (threadIdx.x == 0) {
        int gen = g_gen;
        if (atomicAdd(&g_count, 1) == NCTA - 1) {
            g_count = 0;
            __threadfence();
            g_gen = gen + 1;
        } else {
            while (g_gen == gen) { }
        }
    }
    __syncthreads();
    __threadfence();
}

// One layer tile for this CTA's column slice.
// Warp lanes: j_l = lane>>3 (4 groups), b_l = lane&7 (8 groups).
// Thread tile: M=2 rows (r0 = 8*warp + b_l, r1 = r0+64) x C = Ctot/4 cols.
// A load: 8 distinct rows x 16B = 128B = 1 wavefront (bank-quad-disjoint via APAD).
// W load: 4 distinct j x 16B = 64B = 1 wavefront (bank-quad-disjoint via WPAD).
template<int Ctot, int K, bool SkipPro>
__device__ __forceinline__ void layer_phase(
    Smem* __restrict__ sm,
    const float* __restrict__ Aglob, int Astride,
    const float* __restrict__ Ws,
    float* __restrict__ memS, float* __restrict__ spkS,
    float* __restrict__ spkOut, int outStride, int jbase)
{
    const int tid  = threadIdx.x;
    const int lane = tid & 31;
    const int wrp  = tid >> 5;
    const int j_l  = lane >> 3;          // 0..3
    const int b_l  = lane & 7;           // 0..7
    const int r0   = wrp * 8 + b_l;      // 0..63
    const int r1   = r0 + 64;
    constexpr int C    = Ctot / 4;       // 2 (L0/L1) or 1 (L2)
    constexpr int NC   = K / 64;
    constexpr int WROW = K + WPAD;       // floats per padded W row

    if (!SkipPro) { stage_chunk(sm->a[0], Aglob, Astride); cp_commit(); }

    unsigned long long acc[2][C];
#pragma unroll
    for (int m = 0; m < 2; ++m)
#pragma unroll
        for (int c = 0; c < C; ++c) acc[m][c] = 0ull;

    const ulonglong2* __restrict__ Wp[C];
#pragma unroll
    for (int c = 0; c < C; ++c)
        Wp[c] = (const ulonglong2*)(Ws + (size_t)(j_l * C + c) * WROW);

    for (int ch = 0; ch < NC; ++ch) {
        if (ch + 1 < NC) stage_chunk(sm->a[(ch + 1) & 1], Aglob + (ch + 1) * 64, Astride);
        cp_commit();
        cp_wait1();                      // chunk ch landed; ch+1 in flight
        __syncthreads();

        const float* abuf = sm->a[ch & 1];
        const ulonglong2* __restrict__ A0 = (const ulonglong2*)(abuf + (size_t)r0 * APAD);
        const ulonglong2* __restrict__ A1 = (const ulonglong2*)(abuf + (size_t)r1 * APAD);
        const int wb = ch * 16;
#pragma unroll
        for (int k4 = 0; k4 < 16; ++k4) {
            ulonglong2 a0 = A0[k4];                  // 4 floats of row r0
            ulonglong2 a1 = A1[k4];                  // 4 floats of row r1
#pragma unroll
            for (int c = 0; c < C; ++c) {
                ulonglong2 w = Wp[c][wb + k4];       // 4 floats of col j_l*C+c
                fma2(acc[0][c], a0.x, w.x);
                fma2(acc[0][c], a0.y, w.y);
                fma2(acc[1][c], a1.x, w.x);
                fma2(acc[1][c], a1.y, w.y);
            }
        }
        __syncthreads();                 // all readers done before buffer reuse
    }

    // LIF update: mem*0.5*(1-s) exact (factor in {0,0.5}); one rounded add.
#pragma unroll
    for (int m = 0; m < 2; ++m) {
        int r = (m == 0) ? r0 : r1;
#pragma unroll
        for (int c = 0; c < C; ++c) {
            float lo  = __uint_as_float((unsigned)acc[m][c]);
            float hi  = __uint_as_float((unsigned)(acc[m][c] >> 32));
            float dot = lo + hi;
            int   idx = r * Ctot + j_l * C + c;
            float mv  = memS[idx];
            float sv  = spkS[idx];
            float nm  = mv * (0.5f * (1.0f - sv)) + dot;
            memS[idx] = nm;
            spkS[idx] = (nm > 0.3f) ? 1.0f : 0.0f;
        }
    }

    // Cooperative coalesced spike publish (float4 per 4 cols).
    if (spkOut) {
        __syncthreads();
        constexpr int F4 = Ctot / 4;     // 2 or 1
        for (int i = tid; i < BATCH * F4; i += NTHR) {
            int bb = i / F4, q = i % F4;
            *(float4*)(spkOut + (size_t)bb * outStride + jbase + q * 4) =
                *(const float4*)(spkS + bb * Ctot + q * 4);
        }
    }
}

__global__ __launch_bounds__(NTHR, 1)
void snn_kernel(const float* __restrict__ x,
                const float* __restrict__ w0,
                const float* __restrict__ w1,
                const float* __restrict__ w2,
                float* __restrict__ out)
{
    extern __shared__ char smem_raw[];
    Smem* sm = (Smem*)smem_raw;
    const int cta = blockIdx.x;
    const int tid = threadIdx.x;

    // ---- load this CTA's weight column slices (one-time, padded rows) ----
    for (int i = tid; i < 8 * 512; i += NTHR) {
        int k = i >> 3, jl = i & 7;
        sm->w0[jl * (512 + WPAD) + k] = w0[k * 1024 + cta * 8 + jl];
    }
    for (int i = tid; i < 8 * 1024; i += NTHR) {
        int k = i >> 3, jl = i & 7;
        sm->w1[jl * (1024 + WPAD) + k] = w1[k * 1024 + cta * 8 + jl];
    }
    for (int i = tid; i < 4 * 1024; i += NTHR) {
        int k = i >> 2, jl = i & 3;
        sm->w2[jl * (1024 + WPAD) + k] = w2[k * 512 + cta * 4 + jl];
    }
    // ---- zero private LIF state ----
    for (int i = tid; i < BATCH * 8; i += NTHR) {
        sm->mem0[i] = 0.f; sm->spk0[i] = 0.f;
        sm->mem1[i] = 0.f; sm->spk1[i] = 0.f;
    }
    for (int i = tid; i < BATCH * 4; i += NTHR) {
        sm->mem2[i] = 0.f; sm->spk2[i] = 0.f;
    }

    // ---- transpose x[b][k][t] -> g_xT[t][b][k] (32x32 smem tiles) ----
    {
        float* tile = sm->a[0];
        const int r = tid >> 5, c = tid & 31;
        for (int tl = cta; tl < BATCH * 256; tl += NCTA) {   // uniform per-CTA count
            int b   = tl >> 8;
            int rem = tl & 255;
            int k0  = (rem >> 4) << 5;
            int t0  = (rem & 15) << 5;
            const float* src = x + (size_t)b * (512 * 512);
            __syncthreads();
            for (int rr = r; rr < 32; rr += 8)
                tile[rr * 33 + c] = src[(k0 + rr) * 512 + (t0 + c)];
            __syncthreads();
            for (int rr = r; rr < 32; rr += 8)
                g_xT[(size_t)(t0 + rr) * (BATCH * 512) + b * 512 + (k0 + c)] = tile[c * 33 + rr];
        }
    }
    grid_sync();

    // Prefetch L0(0)'s first chunk (x is dependency-free).
    stage_chunk(sm->a[0], g_xT, 512);
    cp_commit();

    // ---- pipelined time loop: phase p = L0(p) || L1(p-1) || L2(p-2), 1 sync/phase ----
    for (int p = 0; p <= T_STEPS + 1; ++p) {
        if (p) grid_sync();              // publishes phase p-1 spikes

        if (p < T_STEPS)
            layer_phase<8, 512, true>(sm, g_xT + (size_t)p * (BATCH * 512), 512,
                                      sm->w0, sm->mem0, sm->spk0,
                                      g_spk0[p & 1], 1024, cta * 8);
        if (p >= 1 && p <= T_STEPS)
            layer_phase<8, 1024, false>(sm, g_spk0[(p - 1) & 1], 1024,
                                        sm->w1, sm->mem1, sm->spk1,
                                        g_spk1[(p - 1) & 1], 1024, cta * 8);
        if (p >= 2)
            layer_phase<4, 1024, false>(sm, g_spk1[(p - 2) & 1], 1024,
                                        sm->w2, sm->mem2, sm->spk2,
                                        (p == T_STEPS + 1) ? out : (float*)0,
                                        512, cta * 4);

        // Prefetch next phase's L0 chunk 0 before the barrier (x is dep-free;
        // buffer 0 is idle after the last layer's trailing __syncthreads).
        if (p + 1 < T_STEPS) {
            stage_chunk(sm->a[0], g_xT + (size_t)(p + 1) * (BATCH * 512), 512);
            cp_commit();
        }
    }
}

extern "C" void kernel_launch(void* const* d_in, const int* in_sizes, int n_in,
                              void* d_out, int out_size)
{
    const float* x  = (const float*)d_in[0];
    const float* w0 = (const float*)d_in[1];
    const float* w1 = (const float*)d_in[2];
    const float* w2 = (const float*)d_in[3];
    (void)in_sizes; (void)n_in; (void)out_size;

    int smemBytes = (int)sizeof(Smem);   // ~140 KB, needs opt-in
    cudaFuncSetAttribute(snn_kernel, cudaFuncAttributeMaxDynamicSharedMemorySize, smemBytes);
    snn_kernel<<<NCTA, NTHR, smemBytes>>>(x, w0, w1, w2, (float*)d_out);
}

// round 12
// speedup vs baseline: 1.0026x; 1.0026x over previous
#include <cuda_runtime.h>
#include <cstdint>

#define NCTA  128
#define NTHR  256
#define T_STEPS 512
#define BATCH 128
#define APAD  68      // A row stride: 68 % 32 == 4 -> 8 b-lanes hit distinct bank quads
#define WPAD  4       // W row pad: stride C*(K+4) floats -> distinct bank quads for 4 j-lanes

// ---- global scratch (static: no allocation allowed) ----
__device__ float g_xT[T_STEPS * BATCH * 512];     // [t][b][k] time-major input
__device__ float g_spk0[2][BATCH * 1024];         // parity-double-buffered spike planes
__device__ float g_spk1[2][BATCH * 1024];
__device__ int          g_count;
__device__ volatile int g_gen;

struct __align__(16) Smem {
    float w0[8 * (512 + WPAD)];   // [jl][k]  this CTA's 8 cols of W0 (padded rows)
    float w1[8 * (1024 + WPAD)];  // [jl][k]  8 cols of W1
    float w2[4 * (1024 + WPAD)];  // [jl][k]  4 cols of W2
    float a[2][BATCH * APAD];     // double-buffered A chunks [b][64k]
    float mem0[BATCH * 8], spk0[BATCH * 8];
    float mem1[BATCH * 8], spk1[BATCH * 8];
    float mem2[BATCH * 4], spk2[BATCH * 4];
};

// ---- packed dual-fp32 FMA (SASS FFMA2): 2 exact IEEE fp32 FMAs per instr ----
__device__ __forceinline__ void fma2(unsigned long long& d,
                                     unsigned long long a, unsigned long long b) {
    asm("fma.rn.f32x2 %0, %1, %2, %0;" : "+l"(d) : "l"(a), "l"(b));
}

// ---- cp.async helpers ----
__device__ __forceinline__ void cp_async16(void* sdst, const void* gsrc) {
    uint32_t s = (uint32_t)__cvta_generic_to_shared(sdst);
    asm volatile("cp.async.cg.shared.global [%0], [%1], 16;" :: "r"(s), "l"(gsrc) : "memory");
}
__device__ __forceinline__ void cp_commit() {
    asm volatile("cp.async.commit_group;" ::: "memory");
}
__device__ __forceinline__ void cp_wait1() {
    asm volatile("cp.async.wait_group 1;" ::: "memory");
}

// Stage one 64k x 128row A chunk (32 KB) into smem. 8 x 16B per thread.
__device__ __forceinline__ void stage_chunk(float* dst, const float* src, int stride) {
    const int tid = threadIdx.x;
#pragma unroll
    for (int i = 0; i < 8; ++i) {
        int flat = tid + i * NTHR;           // 0..2047 float4 slots
        int br = flat >> 4, k4 = flat & 15;
        cp_async16(dst + br * APAD + k4 * 4, src + (size_t)br * stride + k4 * 4);
    }
}

// ---- grid barrier: 128 CTAs, 1/SM, co-resident by construction ----
__device__ __forceinline__ void grid_sync()
{
    __threadfence();
    __syncthreads();
    if (threadIdx.x == 0) {
        int gen = g_gen;
        if (atomicAdd(&g_count, 1) == NCTA - 1) {
            g_count = 0;
            __threadfence();
            g_gen = gen + 1;
        } else {
            while (g_gen == gen) { }
        }
    }
    __syncthreads();
    __threadfence();
}

// One layer tile for this CTA's column slice.
// Warp lanes: j_l = lane>>3 (4 groups), b_l = lane&7 (8 groups).
// Thread tile: M=2 rows (r0 = 8*warp + b_l, r1 = r0+64) x C = Ctot/4 cols.
// A load: 8 distinct rows x 16B = 128B = 1 wavefront (bank-quad-disjoint via APAD).
// W load: 4 distinct j x 16B = 64B = 1 wavefront (bank-quad-disjoint via WPAD).
template<int Ctot, int K, bool SkipPro>
__device__ __forceinline__ void layer_phase(
    Smem* __restrict__ sm,
    const float* __restrict__ Aglob, int Astride,
    const float* __restrict__ Ws,
    float* __restrict__ memS, float* __restrict__ spkS,
    float* __restrict__ spkOut, int outStride, int jbase)
{
    const int tid  = threadIdx.x;
    const int lane = tid & 31;
    const int wrp  = tid >> 5;
    const int j_l  = lane >> 3;          // 0..3
    const int b_l  = lane & 7;           // 0..7
    const int r0   = wrp * 8 + b_l;      // 0..63
    const int r1   = r0 + 64;
    constexpr int C    = Ctot / 4;       // 2 (L0/L1) or 1 (L2)
    constexpr int NC   = K / 64;
    constexpr int WROW = K + WPAD;       // floats per padded W row

    if (!SkipPro) { stage_chunk(sm->a[0], Aglob, Astride); cp_commit(); }

    unsigned long long acc[2][C];
#pragma unroll
    for (int m = 0; m < 2; ++m)
#pragma unroll
        for (int c = 0; c < C; ++c) acc[m][c] = 0ull;

    const ulonglong2* __restrict__ Wp[C];
#pragma unroll
    for (int c = 0; c < C; ++c)
        Wp[c] = (const ulonglong2*)(Ws + (size_t)(j_l * C + c) * WROW);

    for (int ch = 0; ch < NC; ++ch) {
        if (ch + 1 < NC) stage_chunk(sm->a[(ch + 1) & 1], Aglob + (ch + 1) * 64, Astride);
        cp_commit();
        cp_wait1();                      // chunk ch landed; ch+1 in flight
        __syncthreads();

        const float* abuf = sm->a[ch & 1];
        const ulonglong2* __restrict__ A0 = (const ulonglong2*)(abuf + (size_t)r0 * APAD);
        const ulonglong2* __restrict__ A1 = (const ulonglong2*)(abuf + (size_t)r1 * APAD);
        const int wb = ch * 16;
#pragma unroll
        for (int k4 = 0; k4 < 16; ++k4) {
            ulonglong2 a0 = A0[k4];                  // 4 floats of row r0
            ulonglong2 a1 = A1[k4];                  // 4 floats of row r1
#pragma unroll
            for (int c = 0; c < C; ++c) {
                ulonglong2 w = Wp[c][wb + k4];       // 4 floats of col j_l*C+c
                fma2(acc[0][c], a0.x, w.x);
                fma2(acc[0][c], a0.y, w.y);
                fma2(acc[1][c], a1.x, w.x);
                fma2(acc[1][c], a1.y, w.y);
            }
        }
        __syncthreads();                 // all readers done before buffer reuse
    }

    // LIF update: mem*0.5*(1-s) exact (factor in {0,0.5}); one rounded add.
#pragma unroll
    for (int m = 0; m < 2; ++m) {
        int r = (m == 0) ? r0 : r1;
#pragma unroll
        for (int c = 0; c < C; ++c) {
            float lo  = __uint_as_float((unsigned)acc[m][c]);
            float hi  = __uint_as_float((unsigned)(acc[m][c] >> 32));
            float dot = lo + hi;
            int   idx = r * Ctot + j_l * C + c;
            float mv  = memS[idx];
            float sv  = spkS[idx];
            float nm  = mv * (0.5f * (1.0f - sv)) + dot;
            memS[idx] = nm;
            spkS[idx] = (nm > 0.3f) ? 1.0f : 0.0f;
        }
    }

    // Cooperative coalesced spike publish (float4 per 4 cols).
    if (spkOut) {
        __syncthreads();
        constexpr int F4 = Ctot / 4;     // 2 or 1
        for (int i = tid; i < BATCH * F4; i += NTHR) {
            int bb = i / F4, q = i % F4;
            *(float4*)(spkOut + (size_t)bb * outStride + jbase + q * 4) =
                *(const float4*)(spkS + bb * Ctot + q * 4);
        }
    }
}

__global__ __launch_bounds__(NTHR, 1)
void snn_kernel(const float* __restrict__ x,
                const float* __restrict__ w0,
                const float* __restrict__ w1,
                const float* __restrict__ w2,
                float* __restrict__ out)
{
    extern __shared__ char smem_raw[];
    Smem* sm = (Smem*)smem_raw;
    const int cta = blockIdx.x;
    const int tid = threadIdx.x;

    // ---- load this CTA's weight column slices (one-time, padded rows) ----
    for (int i = tid; i < 8 * 512; i += NTHR) {
        int k = i >> 3, jl = i & 7;
        sm->w0[jl * (512 + WPAD) + k] = w0[k * 1024 + cta * 8 + jl];
    }
    for (int i = tid; i < 8 * 1024; i += NTHR) {
        int k = i >> 3, jl = i & 7;
        sm->w1[jl * (1024 + WPAD) + k] = w1[k * 1024 + cta * 8 + jl];
    }
    for (int i = tid; i < 4 * 1024; i += NTHR) {
        int k = i >> 2, jl = i & 3;
        sm->w2[jl * (1024 + WPAD) + k] = w2[k * 512 + cta * 4 + jl];
    }
    // ---- zero private LIF state ----
    for (int i = tid; i < BATCH * 8; i += NTHR) {
        sm->mem0[i] = 0.f; sm->spk0[i] = 0.f;
        sm->mem1[i] = 0.f; sm->spk1[i] = 0.f;
    }
    for (int i = tid; i < BATCH * 4; i += NTHR) {
        sm->mem2[i] = 0.f; sm->spk2[i] = 0.f;
    }

    // ---- transpose x[b][k][t] -> g_xT[t][b][k] (32x32 smem tiles) ----
    {
        float* tile = sm->a[0];
        const int r = tid >> 5, c = tid & 31;
        for (int tl = cta; tl < BATCH * 256; tl += NCTA) {   // uniform per-CTA count
            int b   = tl >> 8;
            int rem = tl & 255;
            int k0  = (rem >> 4) << 5;
            int t0  = (rem & 15) << 5;
            const float* src = x + (size_t)b * (512 * 512);
            __syncthreads();
            for (int rr = r; rr < 32; rr += 8)
                tile[rr * 33 + c] = src[(k0 + rr) * 512 + (t0 + c)];
            __syncthreads();
            for (int rr = r; rr < 32; rr += 8)
                g_xT[(size_t)(t0 + rr) * (BATCH * 512) + b * 512 + (k0 + c)] = tile[c * 33 + rr];
        }
    }
    grid_sync();

    // Prefetch L0(0)'s first chunk (x is dependency-free).
    stage_chunk(sm->a[0], g_xT, 512);
    cp_commit();

    // ---- pipelined time loop: phase p = L0(p) || L1(p-1) || L2(p-2), 1 sync/phase ----
    for (int p = 0; p <= T_STEPS + 1; ++p) {
        if (p) grid_sync();              // publishes phase p-1 spikes

        if (p < T_STEPS)
            layer_phase<8, 512, true>(sm, g_xT + (size_t)p * (BATCH * 512), 512,
                                      sm->w0, sm->mem0, sm->spk0,
                                      g_spk0[p & 1], 1024, cta * 8);
        if (p >= 1 && p <= T_STEPS)
            layer_phase<8, 1024, false>(sm, g_spk0[(p - 1) & 1], 1024,
                                        sm->w1, sm->mem1, sm->spk1,
                                        g_spk1[(p - 1) & 1], 1024, cta * 8);
        if (p >= 2)
            layer_phase<4, 1024, false>(sm, g_spk1[(p - 2) & 1], 1024,
                                        sm->w2, sm->mem2, sm->spk2,
                                        (p == T_STEPS + 1) ? out : (float*)0,
                                        512, cta * 4);

        // Prefetch next phase's L0 chunk 0 before the barrier (x is dep-free;
        // buffer 0 is idle after the last layer's trailing __syncthreads).
        if (p + 1 < T_STEPS) {
            stage_chunk(sm->a[0], g_xT + (size_t)(p + 1) * (BATCH * 512), 512);
            cp_commit();
        }
    }
}

extern "C" void kernel_launch(void* const* d_in, const int* in_sizes, int n_in,
                              void* d_out, int out_size)
{
    const float* x  = (const float*)d_in[0];
    const float* w0 = (const float*)d_in[1];
    const float* w1 = (const float*)d_in[2];
    const float* w2 = (const float*)d_in[3];
    (void)in_sizes; (void)n_in; (void)out_size;

    int smemBytes = (int)sizeof(Smem);   // ~140 KB, needs opt-in
    cudaFuncSetAttribute(snn_kernel, cudaFuncAttributeMaxDynamicSharedMemorySize, smemBytes);
    snn_kernel<<<NCTA, NTHR, smemBytes>>>(x, w0, w1, w2, (float*)d_out);
}

// round 17
// speedup vs baseline: 1.3358x; 1.3324x over previous
#include <cuda_runtime.h>
#include <cstdint>

#define NCTA  128
#define NTHR  256
#define T_STEPS 512
#define BATCH 128

typedef unsigned long long ull;

// ---- global scratch (static: no allocation allowed) ----
__device__ float g_xT[(size_t)T_STEPS * BATCH * 512];      // [t][b][k] time-major input
__device__ float g_I0[(size_t)T_STEPS * BATCH * 1024];     // [t][b][j] precomputed x@W0
__device__ unsigned g_bits0[2][32 * 128];                  // spike planes, word-major [w][b]
__device__ unsigned g_bits1[2][32 * 128];
__device__ int          g_count;
__device__ volatile int g_gen;

// ---- packed fp32 helpers ----
__device__ __forceinline__ void fma2(ull& d, ull a, ull b) {   // d = a*b + d (2 fp32 lanes)
    asm("fma.rn.f32x2 %0, %1, %2, %0;" : "+l"(d) : "l"(a), "l"(b));
}
__device__ __forceinline__ void pred2x2(ull& a0, ull& a1, unsigned m, ull w0, ull w1) {
    // if (m) { a0 += w0; a1 += w1; }  — each lane an exact IEEE fp32 add
    asm("{\n\t.reg .pred p;\n\tsetp.ne.u32 p, %2, 0;\n\t"
        "@p add.rn.f32x2 %0, %0, %3;\n\t@p add.rn.f32x2 %1, %1, %4;\n\t}"
        : "+l"(a0), "+l"(a1) : "r"(m), "l"(w0), "l"(w1));
}
__device__ __forceinline__ void pred2(ull& a0, unsigned m, ull w0) {
    asm("{\n\t.reg .pred p;\n\tsetp.ne.u32 p, %1, 0;\n\t"
        "@p add.rn.f32x2 %0, %0, %2;\n\t}" : "+l"(a0) : "r"(m), "l"(w0));
}
__device__ __forceinline__ ull dupf(float f) {
    ull d; unsigned u = __float_as_uint(f);
    asm("mov.b64 %0, {%1, %1};" : "=l"(d) : "r"(u));
    return d;
}
__device__ __forceinline__ ull pack2(float lo, float hi) {
    ull d;
    asm("mov.b64 %0, {%1, %2};" : "=l"(d) : "r"(__float_as_uint(lo)), "r"(__float_as_uint(hi)));
    return d;
}
__device__ __forceinline__ float lo32(ull v) { return __uint_as_float((unsigned)v); }
__device__ __forceinline__ float hi32(ull v) { return __uint_as_float((unsigned)(v >> 32)); }
// decay selector: lane = spike-bit ? 0.0 : 0.5   (reset-by-spike, exact)
__device__ __forceinline__ ull dsel(unsigned nib, int b0, int b1) {
    float lo = ((nib >> b0) & 1) ? 0.0f : 0.5f;
    float hi = ((nib >> b1) & 1) ? 0.0f : 0.5f;
    return pack2(lo, hi);
}
// spike bits of a packed pair: bit0 = lo>THRESH, bit1 = hi>THRESH
__device__ __forceinline__ unsigned sp2(ull v) {
    unsigned r = 0;
    if (lo32(v) > 0.3f) r = 1;
    if (hi32(v) > 0.3f) r |= 2;
    return r;
}

// ---- grid barrier: 128 CTAs, 1/SM, co-resident by construction ----
__device__ __forceinline__ void grid_sync()
{
    __threadfence();
    __syncthreads();
    if (threadIdx.x == 0) {
        int gen = g_gen;
        if (atomicAdd(&g_count, 1) == NCTA - 1) {
            g_count = 0;
            __threadfence();
            g_gen = gen + 1;
        } else {
            while (g_gen == gen) { }
        }
    }
    __syncthreads();
    __threadfence();
}

// ================= kernel 1: transpose x[b][k][t] -> g_xT[t][b][k] =================
__global__ __launch_bounds__(256)
void transpose_kernel(const float* __restrict__ x)
{
    __shared__ float tile[32 * 33];
    const int tl  = blockIdx.x;             // 0..32767
    const int b   = tl >> 8;
    const int rem = tl & 255;
    const int k0  = (rem >> 4) << 5;
    const int t0  = (rem & 15) << 5;
    const int r   = threadIdx.x >> 5, c = threadIdx.x & 31;
    const float* src = x + (size_t)b * (512 * 512);
#pragma unroll
    for (int q = r; q < 32; q += 8)
        tile[q * 33 + c] = src[(size_t)(k0 + q) * 512 + t0 + c];
    __syncthreads();
#pragma unroll
    for (int q = r; q < 32; q += 8)
        g_xT[(size_t)(t0 + q) * (BATCH * 512) + b * 512 + k0 + c] = tile[c * 33 + q];
}

// ================= kernel 2: I0[t] = xT[t] @ W0 (FFMA2 GEMM) =================
// 8192 CTAs; each computes one 128-row x 64-col tile, K=512.
__global__ __launch_bounds__(256)
void i0_gemm_kernel(const float* __restrict__ w0)
{
    __shared__ float sA[32 * 132];          // [k][row] k-major A chunk
    __shared__ float sW[32 * 68];           // [k][col] W chunk
    const int tid = threadIdx.x;
    const int t   = blockIdx.x >> 4;        // time step
    const int jb  = (blockIdx.x & 15) << 6; // col block base
    const int tm  = tid >> 4, tn = tid & 15;
    const float* Ab = g_xT + (size_t)t * (BATCH * 512);

    ull acc[4][4];
#pragma unroll
    for (int pr = 0; pr < 4; ++pr)
#pragma unroll
        for (int c = 0; c < 4; ++c) acc[pr][c] = 0ull;

    for (int kc = 0; kc < 512; kc += 32) {
#pragma unroll
        for (int q = 0; q < 4; ++q) {       // stage A 128x32 (k-major)
            int flat = tid + q * 256;
            int row = flat >> 3, kq = flat & 7;
            float4 v = *(const float4*)(Ab + (size_t)row * 512 + kc + kq * 4);
            sA[(kq * 4 + 0) * 132 + row] = v.x;
            sA[(kq * 4 + 1) * 132 + row] = v.y;
            sA[(kq * 4 + 2) * 132 + row] = v.z;
            sA[(kq * 4 + 3) * 132 + row] = v.w;
        }
#pragma unroll
        for (int q = 0; q < 2; ++q) {       // stage W 32x64
            int flat = tid + q * 256;
            int kk = flat >> 4, c4 = (flat & 15) << 2;
            *(float4*)(sW + kk * 68 + c4) =
                *(const float4*)(w0 + (size_t)(kc + kk) * 1024 + jb + c4);
        }
        __syncthreads();
#pragma unroll
        for (int k = 0; k < 32; ++k) {
            ulonglong2 aA = *(const ulonglong2*)(sA + k * 132 + tm * 8);
            ulonglong2 aB = *(const ulonglong2*)(sA + k * 132 + tm * 8 + 4);
            float4 wv = *(const float4*)(sW + k * 68 + tn * 4);
            ull w0d = dupf(wv.x), w1d = dupf(wv.y), w2d = dupf(wv.z), w3d = dupf(wv.w);
            fma2(acc[0][0], aA.x, w0d); fma2(acc[1][0], aA.y, w0d);
            fma2(acc[2][0], aB.x, w0d); fma2(acc[3][0], aB.y, w0d);
            fma2(acc[0][1], aA.x, w1d); fma2(acc[1][1], aA.y, w1d);
            fma2(acc[2][1], aB.x, w1d); fma2(acc[3][1], aB.y, w1d);
            fma2(acc[0][2], aA.x, w2d); fma2(acc[1][2], aA.y, w2d);
            fma2(acc[2][2], aB.x, w2d); fma2(acc[3][2], aB.y, w2d);
            fma2(acc[0][3], aA.x, w3d); fma2(acc[1][3], aA.y, w3d);
            fma2(acc[2][3], aB.x, w3d); fma2(acc[3][3], aB.y, w3d);
        }
        __syncthreads();
    }
#pragma unroll
    for (int pr = 0; pr < 4; ++pr) {        // epilogue: 8 rows x 4 cols per thread
        int row = t * 128 + tm * 8 + pr * 2;
        float4 lo4 = make_float4(lo32(acc[pr][0]), lo32(acc[pr][1]),
                                 lo32(acc[pr][2]), lo32(acc[pr][3]));
        float4 hi4 = make_float4(hi32(acc[pr][0]), hi32(acc[pr][1]),
                                 hi32(acc[pr][2]), hi32(acc[pr][3]));
        *(float4*)(g_I0 + (size_t)row * 1024 + jb + tn * 4) = lo4;
        *(float4*)(g_I0 + (size_t)(row + 1) * 1024 + jb + tn * 4) = hi4;
    }
}

// ================= kernel 3: persistent SNN loop =================
// 128 CTAs x 256 thr. Thread (r = tid&127, h = tid>>7) owns:
//   L0/L1: cols cta*8 + 4h + {0..3}  (2 packed pairs)    L2: cols cta*4 + 2h + {0,1}
// Phase p computes L0(p) || L1(p-1) || L2(p-2); one grid_sync per phase.
__global__ __launch_bounds__(NTHR, 1)
void snn_loop_kernel(const float* __restrict__ w1,
                     const float* __restrict__ w2,
                     float* __restrict__ out)
{
    extern __shared__ float smem[];
    ull*      wsm1 = (ull*)smem;               // [1024][4] col-pairs of W1 (32 KB)
    ull*      wsm2 = (ull*)(smem + 8192);      // [1024][2] col-pairs of W2 (16 KB)
    unsigned* nib0 = (unsigned*)(smem + 12288);
    unsigned* nib1 = nib0 + 128;

    const int cta = blockIdx.x;
    const int tid = threadIdx.x;
    const int r   = tid & 127;
    const int h   = tid >> 7;

    // ---- stage this CTA's W1 (8 cols) / W2 (4 cols), pair-interleaved [k][cols] ----
    {
        float* w1f = (float*)wsm1;
        float* w2f = (float*)wsm2;
#pragma unroll
        for (int q = 0; q < 8; ++q) {
            int flat = tid + q * 256;          // 2048 float4
            int k = flat >> 1, hf = flat & 1;
            *(float4*)(w1f + k * 8 + hf * 4) =
                *(const float4*)(w1 + (size_t)k * 1024 + cta * 8 + hf * 4);
        }
#pragma unroll
        for (int q = 0; q < 4; ++q) {
            int k = tid + q * 256;             // 1024 float4
            *(float4*)(w2f + k * 4) = *(const float4*)(w2 + (size_t)k * 512 + cta * 4);
        }
    }
    __syncthreads();

    // Register-resident LIF state
    ull m0a = 0, m0b = 0;
    ull m1a = 0, m1b = 0;
    ull m2  = 0;
    unsigned s0n = 0, s1n = 0, s2b = 0;

    for (int p = 0; p <= T_STEPS + 1; ++p) {
        if (p) grid_sync();                    // publishes phase p-1 spike planes

        // prefetch I0 for L0(p) early (latency hidden under L1/L2 compute)
        float4 i0 = make_float4(0.f, 0.f, 0.f, 0.f);
        if (p < T_STEPS)
            i0 = __ldcg((const float4*)(g_I0 + ((size_t)p * 128 + r) * 1024 + cta * 8 + h * 4));

        // ---- L1(p-1): dot over spk0 bit plane, 1024 k ----
        if (p >= 1 && p <= T_STEPS) {
            const unsigned* pl = g_bits0[(p - 1) & 1];
            ull a0 = 0, a1 = 0;
            unsigned bw = __ldcg(pl + r);
            for (int w = 0; w < 32; ++w) {
                unsigned nxt = (w < 31) ? __ldcg(pl + (w + 1) * 128 + r) : 0u;
                const char* wk = (const char*)wsm1 + (size_t)(w * 32) * 32 + h * 16;
#pragma unroll
                for (int kk = 0; kk < 32; ++kk) {
                    ulonglong2 wq = *(const ulonglong2*)(wk + kk * 32);
                    pred2x2(a0, a1, bw & (1u << kk), wq.x, wq.y);
                }
                bw = nxt;
            }
            fma2(a0, m1a, dsel(s1n, 0, 1));    // nm = mem*decay_sel + dot
            fma2(a1, m1b, dsel(s1n, 2, 3));
            m1a = a0; m1b = a1;
            s1n = sp2(a0) | (sp2(a1) << 2);
        }

        // ---- L2(p-2): dot over spk1 bit plane, 1024 k ----
        if (p >= 2) {
            const unsigned* pl = g_bits1[(p - 2) & 1];
            ull a0 = 0;
            unsigned bw = __ldcg(pl + r);
            for (int w = 0; w < 32; ++w) {
                unsigned nxt = (w < 31) ? __ldcg(pl + (w + 1) * 128 + r) : 0u;
                const char* wk = (const char*)wsm2 + (size_t)(w * 32) * 16 + h * 8;
#pragma unroll
                for (int kk = 0; kk < 32; ++kk) {
                    ull wq = *(const ull*)(wk + kk * 16);
                    pred2(a0, bw & (1u << kk), wq);
                }
                bw = nxt;
            }
            fma2(a0, m2, dsel(s2b, 0, 1));
            m2  = a0;
            s2b = sp2(a0);
            if (p == T_STEPS + 1) {            // final L2 step: write output spikes
                float2 o;
                o.x = (s2b & 1) ? 1.0f : 0.0f;
                o.y = (s2b & 2) ? 1.0f : 0.0f;
                *(float2*)(out + (size_t)r * 512 + cta * 4 + h * 2) = o;
            }
        }

        // ---- L0(p): register LIF update from precomputed I0 ----
        if (p < T_STEPS) {
            ull i0a = pack2(i0.x, i0.y), i0b = pack2(i0.z, i0.w);
            fma2(i0a, m0a, dsel(s0n, 0, 1));
            fma2(i0b, m0b, dsel(s0n, 2, 3));
            m0a = i0a; m0b = i0b;
            s0n = sp2(i0a) | (sp2(i0b) << 2);
        }

        // ---- publish spike bit planes (1 byte per row per CTA) ----
        if (p <= T_STEPS) {
            if (h == 0) {
                if (p < T_STEPS) nib0[r] = s0n;
                if (p >= 1)      nib1[r] = s1n;
            }
            __syncthreads();
            if (h == 1) {
                if (p < T_STEPS) {
                    unsigned byte = nib0[r] | (s0n << 4);
                    ((unsigned char*)g_bits0[p & 1])[((cta >> 2) * 128 + r) * 4 + (cta & 3)] =
                        (unsigned char)byte;
                }
                if (p >= 1) {
                    unsigned byte = nib1[r] | (s1n << 4);
                    ((unsigned char*)g_bits1[(p - 1) & 1])[((cta >> 2) * 128 + r) * 4 + (cta & 3)] =
                        (unsigned char)byte;
                }
            }
        }
    }
}

extern "C" void kernel_launch(void* const* d_in, const int* in_sizes, int n_in,
                              void* d_out, int out_size)
{
    const float* x  = (const float*)d_in[0];
    const float* w0 = (const float*)d_in[1];
    const float* w1 = (const float*)d_in[2];
    const float* w2 = (const float*)d_in[3];
    (void)in_sizes; (void)n_in; (void)out_size;

    transpose_kernel<<<BATCH * 256, 256>>>(x);
    i0_gemm_kernel<<<T_STEPS * 16, 256>>>(w0);

    int smemBytes = 12544 * 4;   // 50176 B
    cudaFuncSetAttribute(snn_loop_kernel, cudaFuncAttributeMaxDynamicSharedMemorySize, smemBytes);
    snn_loop_kernel<<<NCTA, NTHR, smemBytes>>>(w1, w2, (float*)d_out);
}